// round 12
// baseline (speedup 1.0000x reference)
#include <cuda_runtime.h>
#include <cuda_bf16.h>
#include <cstdint>

#define B_ROWS 32768
#define C_COLS 1000
#define C_PAD  1024
#define FDIM   256

#define TM   32                // rows per CTA (cos tile fully register-resident)
#define KSL  16                // K-slice width (finer granularity)
#define NKSL (FDIM / KSL)      // 16
#define NBUF 3                 // triple buffering, wait_group 2
#define THREADS 512            // 16 warps, each owns 64 cols (8 n-blocks of 8)

#define APAD   264             // A: 256 + 8 bf16 pad -> conflict-free ldmatrix
#define ROWB   (APAD * 2)      // 528 B per A smem row (33*16: aligned)
#define A_BYTES (TM * ROWB)    // 16896
#define BROW   48              // B slice row: 32B data + 16B pad (3*16: aligned, odd phase)
#define B_SLICE (C_PAD * BROW) // 49152 per buffer
#define RS_OFF  (A_BYTES + NBUF * B_SLICE)  // 164352
#define SMEM_TOTAL (RS_OFF + TM * 4)        // 164480 (1 CTA/SM)

// ---- scratch (device global; no runtime allocation) ------------------------
__device__ __nv_bfloat16 g_pb[C_PAD * FDIM];   // normalized prototypes, bf16 (zero-padded)

// ---- helpers ----------------------------------------------------------------
__device__ __forceinline__ uint32_t smem_u32(const void* p) {
    uint32_t a;
    asm("{ .reg .u64 t; cvta.to.shared.u64 t, %1; cvt.u32.u64 %0, t; }" : "=r"(a) : "l"(p));
    return a;
}
__device__ __forceinline__ void ldsm4(uint32_t* r, uint32_t addr) {
    asm volatile("ldmatrix.sync.aligned.m8n8.x4.shared.b16 {%0,%1,%2,%3}, [%4];"
                 : "=r"(r[0]), "=r"(r[1]), "=r"(r[2]), "=r"(r[3]) : "r"(addr));
}
__device__ __forceinline__ void mma16816(float* c, const uint32_t* a, uint32_t b0, uint32_t b1) {
    asm volatile(
        "mma.sync.aligned.m16n8k16.row.col.f32.bf16.bf16.f32 "
        "{%0,%1,%2,%3}, {%4,%5,%6,%7}, {%8,%9}, {%0,%1,%2,%3};"
        : "+f"(c[0]), "+f"(c[1]), "+f"(c[2]), "+f"(c[3])
        : "r"(a[0]), "r"(a[1]), "r"(a[2]), "r"(a[3]), "r"(b0), "r"(b1));
}
__device__ __forceinline__ void cp_async16(uint32_t smem_dst, const void* gptr) {
    asm volatile("cp.async.cg.shared.global [%0], [%1], 16;"
                 :: "r"(smem_dst), "l"(gptr) : "memory");
}
__device__ __forceinline__ void cp_commit() {
    asm volatile("cp.async.commit_group;" ::: "memory");
}
__device__ __forceinline__ void cp_wait2() {
    asm volatile("cp.async.wait_group 2;" ::: "memory");
}

// ---------------------------------------------------------------------------
// Prototype normalize + bf16 convert (1024 padded rows, zero tail).
// ---------------------------------------------------------------------------
__global__ void __launch_bounds__(256) conv_proto_kernel(const float* __restrict__ x) {
    int gw   = (blockIdx.x * blockDim.x + threadIdx.x) >> 5;
    int lane = threadIdx.x & 31;
    if (gw >= C_PAD) return;
    uint4 o4 = {0u, 0u, 0u, 0u};
    if (gw < C_COLS) {
        const float4* r4 = reinterpret_cast<const float4*>(x + (size_t)gw * FDIM);
        float4 a = r4[lane * 2], b = r4[lane * 2 + 1];
        float s = a.x*a.x + a.y*a.y + a.z*a.z + a.w*a.w + b.x*b.x + b.y*b.y + b.z*b.z + b.w*b.w;
#pragma unroll
        for (int o = 16; o; o >>= 1) s += __shfl_xor_sync(0xffffffffu, s, o);
        float inv = 1.0f / fmaxf(sqrtf(s), 1e-12f);
        __nv_bfloat162 p0 = __floats2bfloat162_rn(a.x*inv, a.y*inv);
        __nv_bfloat162 p1 = __floats2bfloat162_rn(a.z*inv, a.w*inv);
        __nv_bfloat162 p2 = __floats2bfloat162_rn(b.x*inv, b.y*inv);
        __nv_bfloat162 p3 = __floats2bfloat162_rn(b.z*inv, b.w*inv);
        o4.x = *reinterpret_cast<uint32_t*>(&p0); o4.y = *reinterpret_cast<uint32_t*>(&p1);
        o4.z = *reinterpret_cast<uint32_t*>(&p2); o4.w = *reinterpret_cast<uint32_t*>(&p3);
    }
    reinterpret_cast<uint4*>(g_pb)[(size_t)gw * 32 + lane] = o4;
}

// ---------------------------------------------------------------------------
// Fused single-pass, fine K-sliced (16 x K=16), triple-buffered warp-local
// cp.async pipelines; no CTA barriers in the mainloop.
// 16 warps; warp owns 32 rows x 64 cols (8 n-blocks of 8 cols).
// ---------------------------------------------------------------------------
__global__ void __launch_bounds__(THREADS, 1) fused_kernel(
    const float* __restrict__ feats,
    const float* __restrict__ dscale,
    const float* __restrict__ temp,
    float* __restrict__ out)
{
    extern __shared__ char smem[];
    char*  smA = smem;
    float* rs  = reinterpret_cast<float*>(smem + RS_OFF);

    const uint32_t sbA  = smem_u32(smA);
    const uint32_t sbB  = sbA + A_BYTES;

    const int tid  = threadIdx.x;
    const int wid  = tid >> 5;         // 0..15
    const int lane = tid & 31;
    const int q    = lane >> 2;        // fragment row-within-8
    const int row0 = blockIdx.x * TM;

    if (tid < TM) rs[tid] = 0.0f;

    // ---- per-warp B k-slice loader: warp's 64 cols x 32B = 2KB/slice.
    // lane l -> col (l>>1)+i*16, chunk (l&1); 4 iterations.
    const char* pbB = reinterpret_cast<const char*>(g_pb);
    const int  colL = wid * 64 + (lane >> 1);
    const int  ckL  = lane & 1;
    auto load_slice = [&](int ks, int buf) {
#pragma unroll
        for (int i = 0; i < 4; i++) {
            int col = colL + i * 16;
            cp_async16(sbB + buf * B_SLICE + col * BROW + ckL * 16,
                       pbB + ((size_t)col * FDIM + ks * KSL + ckL * 8) * 2);
        }
        cp_commit();
    };

    // prologue: prefetch this warp's part of slices 0..2
    load_slice(0, 0);
    load_slice(1, 1);
    load_slice(2, 2);

    // ---- A tile: load fp32, normalize, convert, store bf16 (warp per row) ----
    const float4* f4 = reinterpret_cast<const float4*>(feats);
#pragma unroll
    for (int rr = 0; rr < TM / 16; rr++) {
        int r = wid + rr * 16;
        float4 a = f4[(size_t)(row0 + r) * 64 + lane * 2];
        float4 b = f4[(size_t)(row0 + r) * 64 + lane * 2 + 1];
        float sn = a.x*a.x + a.y*a.y + a.z*a.z + a.w*a.w + b.x*b.x + b.y*b.y + b.z*b.z + b.w*b.w;
#pragma unroll
        for (int o = 16; o; o >>= 1) sn += __shfl_xor_sync(0xffffffffu, sn, o);
        float inv = 1.0f / fmaxf(sqrtf(sn), 1e-12f);
        __nv_bfloat162 p0 = __floats2bfloat162_rn(a.x*inv, a.y*inv);
        __nv_bfloat162 p1 = __floats2bfloat162_rn(a.z*inv, a.w*inv);
        __nv_bfloat162 p2 = __floats2bfloat162_rn(b.x*inv, b.y*inv);
        __nv_bfloat162 p3 = __floats2bfloat162_rn(b.z*inv, b.w*inv);
        uint4 o4;
        o4.x = *reinterpret_cast<uint32_t*>(&p0); o4.y = *reinterpret_cast<uint32_t*>(&p1);
        o4.z = *reinterpret_cast<uint32_t*>(&p2); o4.w = *reinterpret_cast<uint32_t*>(&p3);
        *reinterpret_cast<uint4*>(smA + r * ROWB + lane * 16) = o4;
    }
    __syncthreads();   // A tile + rs init visible; only CTA sync before epilogue

    // A fragment base (lane&15 -> row, lane>>4 -> k-half of 16)
    const uint32_t aBase = sbA + (uint32_t)((lane & 15) * APAD + ((lane >> 4) << 3)) * 2;
    // B fragment base: ldsm4 covers 16 cols x 16 k per jj
    //   g = lane>>3: g0 = cols +0..7 @k0, g1 = cols +0..7 @k8, g2 = +8..15 @k0, g3 = +8..15 @k8
    const int g = lane >> 3, rr8 = lane & 7;
    const uint32_t bOff = (uint32_t)((wid * 64 + (g >> 1) * 8 + rr8) * BROW + (g & 1) * 16);

    // ---- persistent cos accumulators: 8 n-blocks x 2 m-frags x 4 = 64 regs ----
    float acc[8][2][4];
#pragma unroll
    for (int j = 0; j < 8; j++)
#pragma unroll
        for (int i = 0; i < 2; i++)
#pragma unroll
            for (int c = 0; c < 4; c++) acc[j][i][c] = 0.0f;

#pragma unroll
    for (int ks = 0; ks < NKSL; ks++) {
        cp_wait2();          // this warp's slice ks landed (<=2 groups pending)
        __syncwarp();

        uint32_t A0[4], A1[4];
        ldsm4(A0, aBase + ks * KSL * 2);
        ldsm4(A1, aBase + 16 * ROWB + ks * KSL * 2);

        const uint32_t bBase = sbB + (ks % NBUF) * B_SLICE + bOff;

#pragma unroll
        for (int jj = 0; jj < 4; jj++) {
            uint32_t b[4];               // [c0-7@k0, c0-7@k8, c8-15@k0, c8-15@k8]
            ldsm4(b, bBase + jj * 16 * BROW);
            mma16816(acc[2*jj][0],     A0, b[0], b[1]);
            mma16816(acc[2*jj][1],     A1, b[0], b[1]);
            mma16816(acc[2*jj + 1][0], A0, b[2], b[3]);
            mma16816(acc[2*jj + 1][1], A1, b[2], b[3]);
        }
        // refill this warp's cols, 3 slices ahead (warp-private buffer region)
        if (ks + NBUF < NKSL) load_slice(ks + NBUF, (ks + NBUF) % NBUF);
        else                  cp_commit();   // keep group count invariant
    }

    // ---- iso in place + per-row partial sums ----
    const float s = fabsf(__ldg(dscale));
    float rsum[4] = {0.f, 0.f, 0.f, 0.f};
#pragma unroll
    for (int j = 0; j < 8; j++) {
        int col = wid * 64 + j * 8 + (lane & 3) * 2;
#pragma unroll
        for (int i = 0; i < 2; i++) {
            if (col < C_COLS) {
                float* a = acc[j][i];
                a[0] = s * sqrtf(fmaxf(1.0f - a[0], 0.0f));
                a[1] = s * sqrtf(fmaxf(1.0f - a[1], 0.0f));
                a[2] = s * sqrtf(fmaxf(1.0f - a[2], 0.0f));
                a[3] = s * sqrtf(fmaxf(1.0f - a[3], 0.0f));
                rsum[2 * i]     += a[0] + a[1];
                rsum[2 * i + 1] += a[2] + a[3];
            }
        }
    }

    // reduce over the 4 lanes sharing each row, then 16 warps via smem atomics
#pragma unroll
    for (int k = 0; k < 4; k++) {
        float v = rsum[k];
        v += __shfl_xor_sync(0xffffffffu, v, 1);
        v += __shfl_xor_sync(0xffffffffu, v, 2);
        if ((lane & 3) == 0) {
            int rloc = 16 * (k >> 1) + 8 * (k & 1) + q;
            atomicAdd(&rs[rloc], v);
        }
    }
    __syncthreads();

    // ---- final store: logits = -(iso + mean)/T, straight from registers ----
    const float itT = 1.0f / __ldg(temp);
    float mean[4];
#pragma unroll
    for (int k = 0; k < 4; k++)
        mean[k] = rs[16 * (k >> 1) + 8 * (k & 1) + q] * (1.0f / (float)C_COLS);

#pragma unroll
    for (int j = 0; j < 8; j++) {
        int col = wid * 64 + j * 8 + (lane & 3) * 2;
#pragma unroll
        for (int i = 0; i < 2; i++) {
            if (col < C_COLS) {
                int r0 = row0 + 16 * i + q;
                const float* a = acc[j][i];
                float2 v0 = make_float2(-(a[0] + mean[2*i])     * itT,
                                        -(a[1] + mean[2*i])     * itT);
                float2 v1 = make_float2(-(a[2] + mean[2*i + 1]) * itT,
                                        -(a[3] + mean[2*i + 1]) * itT);
                *reinterpret_cast<float2*>(&out[(size_t)r0 * C_COLS + col])       = v0;
                *reinterpret_cast<float2*>(&out[(size_t)(r0 + 8) * C_COLS + col]) = v1;
            }
        }
    }
}

// ---------------------------------------------------------------------------
extern "C" void kernel_launch(void* const* d_in, const int* in_sizes, int n_in,
                              void* d_out, int out_size)
{
    const float* feats  = (const float*)d_in[0];
    const float* protos = (const float*)d_in[1];
    const float* ds     = (const float*)d_in[2];
    const float* temp   = (const float*)d_in[3];
    float* out = (float*)d_out;

    cudaFuncSetAttribute(fused_kernel,
                         cudaFuncAttributeMaxDynamicSharedMemorySize, SMEM_TOTAL);

    conv_proto_kernel<<<C_PAD / 8, 256>>>(protos);
    fused_kernel<<<B_ROWS / TM, THREADS, SMEM_TOTAL>>>(feats, ds, temp, out);
}

// round 13
// speedup vs baseline: 1.5139x; 1.5139x over previous
#include <cuda_runtime.h>
#include <cuda_bf16.h>
#include <cstdint>

#define B_ROWS 32768
#define C_COLS 1000
#define C_PAD  1024
#define FDIM   256

#define TM   32                // rows per CTA (cos tile fully register-resident)
#define KSL  32                // K-slice width
#define NKSL (FDIM / KSL)      // 8
#define NBUF 3                 // triple buffering, wait_group 2
#define THREADS 512            // 16 warps, each owns 64 cols (8 n-blocks of 8)

#define APAD   264             // A: 256 + 8 bf16 pad -> conflict-free ldmatrix
#define ROWB   (APAD * 2)      // 528 B per A smem row
#define A_BYTES (TM * ROWB)    // 16896
// B slice in SMEM: [k 0..31][1024 cols] as 16 warp regions of 32 k-rows x 128B,
// 16B segs XOR-swizzled by (k&7) -> conflict-free stores and ldmatrix.trans reads
#define B_SLICE (C_PAD * KSL * 2)           // 65536 per buffer
#define RS_OFF  (A_BYTES + NBUF * B_SLICE)  // 213504
#define SMEM_TOTAL (RS_OFF + TM * 4)        // 213632 (1 CTA/SM)

// ---- scratch (device globals; no runtime allocation) ------------------------
__device__ __nv_bfloat16 g_pb [C_PAD * FDIM];   // normalized protos, [c][k]
__device__ __nv_bfloat16 g_pbt[FDIM * C_PAD];   // transposed,        [k][c]

// ---- helpers ----------------------------------------------------------------
__device__ __forceinline__ uint32_t smem_u32(const void* p) {
    uint32_t a;
    asm("{ .reg .u64 t; cvta.to.shared.u64 t, %1; cvt.u32.u64 %0, t; }" : "=r"(a) : "l"(p));
    return a;
}
__device__ __forceinline__ void ldsm4(uint32_t* r, uint32_t addr) {
    asm volatile("ldmatrix.sync.aligned.m8n8.x4.shared.b16 {%0,%1,%2,%3}, [%4];"
                 : "=r"(r[0]), "=r"(r[1]), "=r"(r[2]), "=r"(r[3]) : "r"(addr));
}
__device__ __forceinline__ void ldsm4t(uint32_t* r, uint32_t addr) {
    asm volatile("ldmatrix.sync.aligned.m8n8.x4.trans.shared.b16 {%0,%1,%2,%3}, [%4];"
                 : "=r"(r[0]), "=r"(r[1]), "=r"(r[2]), "=r"(r[3]) : "r"(addr));
}
__device__ __forceinline__ void mma16816(float* c, const uint32_t* a, uint32_t b0, uint32_t b1) {
    asm volatile(
        "mma.sync.aligned.m16n8k16.row.col.f32.bf16.bf16.f32 "
        "{%0,%1,%2,%3}, {%4,%5,%6,%7}, {%8,%9}, {%0,%1,%2,%3};"
        : "+f"(c[0]), "+f"(c[1]), "+f"(c[2]), "+f"(c[3])
        : "r"(a[0]), "r"(a[1]), "r"(a[2]), "r"(a[3]), "r"(b0), "r"(b1));
}
__device__ __forceinline__ void cp_async16(uint32_t smem_dst, const void* gptr) {
    asm volatile("cp.async.cg.shared.global [%0], [%1], 16;"
                 :: "r"(smem_dst), "l"(gptr) : "memory");
}
__device__ __forceinline__ void cp_commit() {
    asm volatile("cp.async.commit_group;" ::: "memory");
}
__device__ __forceinline__ void cp_wait2() {
    asm volatile("cp.async.wait_group 2;" ::: "memory");
}

// ---------------------------------------------------------------------------
// Prototype normalize + bf16 convert (1024 padded rows, zero tail) -> g_pb.
// ---------------------------------------------------------------------------
__global__ void __launch_bounds__(256) conv_proto_kernel(const float* __restrict__ x) {
    int gw   = (blockIdx.x * blockDim.x + threadIdx.x) >> 5;
    int lane = threadIdx.x & 31;
    if (gw >= C_PAD) return;
    uint4 o4 = {0u, 0u, 0u, 0u};
    if (gw < C_COLS) {
        const float4* r4 = reinterpret_cast<const float4*>(x + (size_t)gw * FDIM);
        float4 a = r4[lane * 2], b = r4[lane * 2 + 1];
        float s = a.x*a.x + a.y*a.y + a.z*a.z + a.w*a.w + b.x*b.x + b.y*b.y + b.z*b.z + b.w*b.w;
#pragma unroll
        for (int o = 16; o; o >>= 1) s += __shfl_xor_sync(0xffffffffu, s, o);
        float inv = 1.0f / fmaxf(sqrtf(s), 1e-12f);
        __nv_bfloat162 p0 = __floats2bfloat162_rn(a.x*inv, a.y*inv);
        __nv_bfloat162 p1 = __floats2bfloat162_rn(a.z*inv, a.w*inv);
        __nv_bfloat162 p2 = __floats2bfloat162_rn(b.x*inv, b.y*inv);
        __nv_bfloat162 p3 = __floats2bfloat162_rn(b.z*inv, b.w*inv);
        o4.x = *reinterpret_cast<uint32_t*>(&p0); o4.y = *reinterpret_cast<uint32_t*>(&p1);
        o4.z = *reinterpret_cast<uint32_t*>(&p2); o4.w = *reinterpret_cast<uint32_t*>(&p3);
    }
    reinterpret_cast<uint4*>(g_pb)[(size_t)gw * 32 + lane] = o4;
}

// ---------------------------------------------------------------------------
// 32x32 tile transpose g_pb[c][k] -> g_pbt[k][c].  grid (32, 8), 256 threads.
// ---------------------------------------------------------------------------
__global__ void __launch_bounds__(256) transpose_pb_kernel() {
    __shared__ uint16_t tile[32][34];    // 34: odd 4B stride -> conflict-free col read
    const int c0 = blockIdx.x * 32;
    const int k0 = blockIdx.y * 32;
    const int tx = threadIdx.x & 31;
    const int ty = threadIdx.x >> 5;     // 0..7
    const uint16_t* src = reinterpret_cast<const uint16_t*>(g_pb);
    uint16_t*       dst = reinterpret_cast<uint16_t*>(g_pbt);
#pragma unroll
    for (int i = 0; i < 4; i++) {
        int c = ty + i * 8;
        tile[c][tx] = src[(size_t)(c0 + c) * FDIM + k0 + tx];
    }
    __syncthreads();
#pragma unroll
    for (int i = 0; i < 4; i++) {
        int k = ty + i * 8;
        dst[(size_t)(k0 + k) * C_PAD + c0 + tx] = tile[tx][k];
    }
}

// ---------------------------------------------------------------------------
// Fused single-pass, K-sliced (8 x K=32), triple-buffered warp-local cp.async
// pipelines on transposed B; no CTA barriers in the mainloop.
// 16 warps; warp owns 32 rows x 64 cols (8 n-blocks of 8 cols).
// ---------------------------------------------------------------------------
__global__ void __launch_bounds__(THREADS, 1) fused_kernel(
    const float* __restrict__ feats,
    const float* __restrict__ dscale,
    const float* __restrict__ temp,
    float* __restrict__ out)
{
    extern __shared__ char smem[];
    char*  smA = smem;
    float* rs  = reinterpret_cast<float*>(smem + RS_OFF);

    const uint32_t sbA  = smem_u32(smA);
    const uint32_t sbB  = sbA + A_BYTES;

    const int tid  = threadIdx.x;
    const int wid  = tid >> 5;         // 0..15
    const int lane = tid & 31;
    const int q    = lane >> 2;        // fragment row-within-8
    const int row0 = blockIdx.x * TM;

    if (tid < TM) rs[tid] = 0.0f;

    // ---- per-warp B k-slice loader: 32 k-rows x 128B = 4KB, coalesced.
    // iter i: lanes cover 4 k-rows (lane>>3) x 8 segs (lane&7); dst seg XOR (k&7).
    const char* pbt = reinterpret_cast<const char*>(g_pbt);
    const uint32_t wOff = (uint32_t)(wid * 4096);
    auto load_slice = [&](int ks, int buf) {
#pragma unroll
        for (int i = 0; i < 8; i++) {
            int kk = i * 4 + (lane >> 3);
            int s  = lane & 7;
            uint32_t dstA = sbB + buf * B_SLICE + wOff + (uint32_t)(kk * 128)
                          + (uint32_t)((s ^ (kk & 7)) << 4);
            cp_async16(dstA, pbt + ((size_t)(ks * KSL + kk) * C_PAD + wid * 64 + s * 8) * 2);
        }
        cp_commit();
    };

    // prologue: prefetch this warp's part of slices 0..2
    load_slice(0, 0);
    load_slice(1, 1);
    load_slice(2, 2);

    // ---- A tile: load fp32, normalize, convert, store bf16 (warp per row) ----
    const float4* f4 = reinterpret_cast<const float4*>(feats);
#pragma unroll
    for (int rr = 0; rr < TM / 16; rr++) {
        int r = wid + rr * 16;
        float4 a = f4[(size_t)(row0 + r) * 64 + lane * 2];
        float4 b = f4[(size_t)(row0 + r) * 64 + lane * 2 + 1];
        float sn = a.x*a.x + a.y*a.y + a.z*a.z + a.w*a.w + b.x*b.x + b.y*b.y + b.z*b.z + b.w*b.w;
#pragma unroll
        for (int o = 16; o; o >>= 1) sn += __shfl_xor_sync(0xffffffffu, sn, o);
        float inv = 1.0f / fmaxf(sqrtf(sn), 1e-12f);
        __nv_bfloat162 p0 = __floats2bfloat162_rn(a.x*inv, a.y*inv);
        __nv_bfloat162 p1 = __floats2bfloat162_rn(a.z*inv, a.w*inv);
        __nv_bfloat162 p2 = __floats2bfloat162_rn(b.x*inv, b.y*inv);
        __nv_bfloat162 p3 = __floats2bfloat162_rn(b.z*inv, b.w*inv);
        uint4 o4;
        o4.x = *reinterpret_cast<uint32_t*>(&p0); o4.y = *reinterpret_cast<uint32_t*>(&p1);
        o4.z = *reinterpret_cast<uint32_t*>(&p2); o4.w = *reinterpret_cast<uint32_t*>(&p3);
        *reinterpret_cast<uint4*>(smA + r * ROWB + lane * 16) = o4;
    }
    __syncthreads();   // A tile + rs init visible; only CTA sync before epilogue

    // A fragment base (lane&15 -> row, lane>>4 -> k-half)
    const uint32_t aBase = sbA + (uint32_t)((lane & 15) * APAD + ((lane >> 4) << 3)) * 2;
    // B fragment row base: lane = k-row (0..31); seg chosen per n-block j with XOR swizzle
    const uint32_t bRow = wOff + (uint32_t)(lane * 128);
    const int l8 = lane & 7;

    // ---- persistent cos accumulators: 8 n-blocks x 2 m-frags x 4 = 64 regs ----
    float acc[8][2][4];
#pragma unroll
    for (int j = 0; j < 8; j++)
#pragma unroll
        for (int i = 0; i < 2; i++)
#pragma unroll
            for (int c = 0; c < 4; c++) acc[j][i][c] = 0.0f;

#pragma unroll
    for (int ks = 0; ks < NKSL; ks++) {
        cp_wait2();          // this warp's slice ks landed (<=2 groups pending)
        __syncwarp();

        // A fragments: [m2][k2], reused across 8 n-blocks
        uint32_t A00[4], A01[4], A10[4], A11[4];
        ldsm4(A00, aBase + (ks * KSL) * 2);
        ldsm4(A01, aBase + (ks * KSL + 16) * 2);
        ldsm4(A10, aBase + 16 * ROWB + (ks * KSL) * 2);
        ldsm4(A11, aBase + 16 * ROWB + (ks * KSL + 16) * 2);

        const uint32_t bBase = sbB + (ks % NBUF) * B_SLICE + bRow;

#pragma unroll
        for (int j = 0; j < 8; j++) {
            uint32_t b[4];   // trans: [k0-7, k8-15, k16-23, k24-31] x 8 cols
            ldsm4t(b, bBase + (uint32_t)((j ^ l8) << 4));
            mma16816(acc[j][0], A00, b[0], b[1]);
            mma16816(acc[j][1], A10, b[0], b[1]);
            mma16816(acc[j][0], A01, b[2], b[3]);
            mma16816(acc[j][1], A11, b[2], b[3]);
        }
        // refill this warp's cols, 3 slices ahead (buffer just consumed)
        if (ks + NBUF < NKSL) load_slice(ks + NBUF, (ks + NBUF) % NBUF);
        else                  cp_commit();   // keep group count invariant
    }

    // ---- iso in place + per-row partial sums ----
    const float s = fabsf(__ldg(dscale));
    float rsum[4] = {0.f, 0.f, 0.f, 0.f};
#pragma unroll
    for (int j = 0; j < 8; j++) {
        int col = wid * 64 + j * 8 + (lane & 3) * 2;
#pragma unroll
        for (int i = 0; i < 2; i++) {
            if (col < C_COLS) {
                float* a = acc[j][i];
                a[0] = s * sqrtf(fmaxf(1.0f - a[0], 0.0f));
                a[1] = s * sqrtf(fmaxf(1.0f - a[1], 0.0f));
                a[2] = s * sqrtf(fmaxf(1.0f - a[2], 0.0f));
                a[3] = s * sqrtf(fmaxf(1.0f - a[3], 0.0f));
                rsum[2 * i]     += a[0] + a[1];
                rsum[2 * i + 1] += a[2] + a[3];
            }
        }
    }

    // reduce over the 4 lanes sharing each row, then 16 warps via smem atomics
#pragma unroll
    for (int k = 0; k < 4; k++) {
        float v = rsum[k];
        v += __shfl_xor_sync(0xffffffffu, v, 1);
        v += __shfl_xor_sync(0xffffffffu, v, 2);
        if ((lane & 3) == 0) {
            int rloc = 16 * (k >> 1) + 8 * (k & 1) + q;
            atomicAdd(&rs[rloc], v);
        }
    }
    __syncthreads();

    // ---- final store: logits = -(iso + mean)/T, straight from registers ----
    const float itT = 1.0f / __ldg(temp);
    float mean[4];
#pragma unroll
    for (int k = 0; k < 4; k++)
        mean[k] = rs[16 * (k >> 1) + 8 * (k & 1) + q] * (1.0f / (float)C_COLS);

#pragma unroll
    for (int j = 0; j < 8; j++) {
        int col = wid * 64 + j * 8 + (lane & 3) * 2;
#pragma unroll
        for (int i = 0; i < 2; i++) {
            if (col < C_COLS) {
                int r0 = row0 + 16 * i + q;
                const float* a = acc[j][i];
                float2 v0 = make_float2(-(a[0] + mean[2*i])     * itT,
                                        -(a[1] + mean[2*i])     * itT);
                float2 v1 = make_float2(-(a[2] + mean[2*i + 1]) * itT,
                                        -(a[3] + mean[2*i + 1]) * itT);
                *reinterpret_cast<float2*>(&out[(size_t)r0 * C_COLS + col])       = v0;
                *reinterpret_cast<float2*>(&out[(size_t)(r0 + 8) * C_COLS + col]) = v1;
            }
        }
    }
}

// ---------------------------------------------------------------------------
extern "C" void kernel_launch(void* const* d_in, const int* in_sizes, int n_in,
                              void* d_out, int out_size)
{
    const float* feats  = (const float*)d_in[0];
    const float* protos = (const float*)d_in[1];
    const float* ds     = (const float*)d_in[2];
    const float* temp   = (const float*)d_in[3];
    float* out = (float*)d_out;

    cudaFuncSetAttribute(fused_kernel,
                         cudaFuncAttributeMaxDynamicSharedMemorySize, SMEM_TOTAL);

    conv_proto_kernel<<<C_PAD / 8, 256>>>(protos);
    transpose_pb_kernel<<<dim3(C_PAD / 32, FDIM / 32), 256>>>();
    fused_kernel<<<B_ROWS / TM, THREADS, SMEM_TOTAL>>>(feats, ds, temp, out);
}